// round 5
// baseline (speedup 1.0000x reference)
#include <cuda_runtime.h>

#define H 64
#define NV_MAX 100000
#define CAP 80

// device scratch (zero-initialized at load; gemv kernel re-zeros g_cnt each call)
__device__ int g_cnt[NV_MAX];
__device__ int g_slots[(size_t)NV_MAX * CAP];
__device__ __align__(16) float g_agg[(size_t)NV_MAX * H];

__device__ __forceinline__ unsigned long long pk2(float lo, float hi) {
    unsigned long long r;
    asm("mov.b64 %0, {%1, %2};" : "=l"(r) : "f"(lo), "f"(hi));
    return r;
}
__device__ __forceinline__ unsigned long long fma2(unsigned long long a,
                                                   unsigned long long b,
                                                   unsigned long long c) {
    unsigned long long d;
    asm("fma.rn.f32x2 %0, %1, %2, %3;" : "=l"(d) : "l"(a), "l"(b), "l"(c));
    return d;
}
__device__ __forceinline__ unsigned long long add2(unsigned long long a,
                                                   unsigned long long b) {
    unsigned long long d;
    asm("add.rn.f32x2 %0, %1, %2;" : "=l"(d) : "l"(a), "l"(b));
    return d;
}

__global__ void fill_kernel(const int* __restrict__ src,
                            const int* __restrict__ dst, int E) {
    int e = blockIdx.x * blockDim.x + threadIdx.x;
    if (e >= E) return;
    int d = dst[e];
    int s = src[e];
    int idx = atomicAdd(&g_cnt[d], 1);
    if (idx < CAP) g_slots[(long)d * CAP + idx] = s;
}

// Warp per row, no block barriers. Writes S row (sum of gathered x rows)
// coalesced to g_agg.
__global__ void __launch_bounds__(256, 4)
gather_kernel(const float4* __restrict__ x4, int nv) {
    const int lane = threadIdx.x & 31;
    const int w = threadIdx.x >> 5;
    const int c = lane & 15;   // float4 chunk
    const int jg = lane >> 4;  // edge group (0/1)

    __shared__ int s_sl[8][CAP];

    const int row = blockIdx.x * 8 + w;
    if (row >= nv) return;

    int m0 = 0;
    if (lane == 0) m0 = g_cnt[row];
    m0 = __shfl_sync(0xffffffffu, m0, 0);
    int m = min(m0, CAP);
    if (lane < m)      s_sl[w][lane]      = g_slots[(long)row * CAP + lane];
    if (lane + 32 < m) s_sl[w][lane + 32] = g_slots[(long)row * CAP + lane + 32];
    if (lane + 64 < m) s_sl[w][lane + 64] = g_slots[(long)row * CAP + lane + 64];
    __syncwarp();

    // 4 independent LDG.128 in flight per iteration
    float4 a0 = make_float4(0.f, 0.f, 0.f, 0.f);
    float4 a1 = make_float4(0.f, 0.f, 0.f, 0.f);
    float4 a2 = make_float4(0.f, 0.f, 0.f, 0.f);
    float4 a3 = make_float4(0.f, 0.f, 0.f, 0.f);
    int j = jg;
    for (; j + 6 < m; j += 8) {
        float4 v0 = x4[(long)s_sl[w][j]     * 16 + c];
        float4 v1 = x4[(long)s_sl[w][j + 2] * 16 + c];
        float4 v2 = x4[(long)s_sl[w][j + 4] * 16 + c];
        float4 v3 = x4[(long)s_sl[w][j + 6] * 16 + c];
        a0.x += v0.x; a0.y += v0.y; a0.z += v0.z; a0.w += v0.w;
        a1.x += v1.x; a1.y += v1.y; a1.z += v1.z; a1.w += v1.w;
        a2.x += v2.x; a2.y += v2.y; a2.z += v2.z; a2.w += v2.w;
        a3.x += v3.x; a3.y += v3.y; a3.z += v3.z; a3.w += v3.w;
    }
    for (; j < m; j += 2) {
        float4 v0 = x4[(long)s_sl[w][j] * 16 + c];
        a0.x += v0.x; a0.y += v0.y; a0.z += v0.z; a0.w += v0.w;
    }
    a0.x += a1.x + a2.x + a3.x;
    a0.y += a1.y + a2.y + a3.y;
    a0.z += a1.z + a2.z + a3.z;
    a0.w += a1.w + a2.w + a3.w;
    a0.x += __shfl_xor_sync(0xffffffffu, a0.x, 16);
    a0.y += __shfl_xor_sync(0xffffffffu, a0.y, 16);
    a0.z += __shfl_xor_sync(0xffffffffu, a0.z, 16);
    a0.w += __shfl_xor_sync(0xffffffffu, a0.w, 16);
    if (lane < 16)
        reinterpret_cast<float4*>(g_agg)[(long)row * 16 + lane] = a0;
}

// 256 threads = 8 rows per pass, uniform work between barriers.
//  load:   warp w loads S row base+w from g_agg (coalesced), deg from g_cnt
//  GEMV:   warp w computes k in [8w,8w+8) for ALL 8 rows (Wp = 8 b64 regs)
//  epilogue: warp w finishes its row (deg norm, ReLU, LN, store)
__global__ void __launch_bounds__(256, 3)
gemv_ln_kernel(const float* __restrict__ W, const float* __restrict__ b,
               const float* __restrict__ gamma, const float* __restrict__ beta,
               float* __restrict__ out, int nv) {
    const int lane = threadIdx.x & 31;
    const int w = threadIdx.x >> 5;

    unsigned long long Wp[8];
#pragma unroll
    for (int kq = 0; kq < 8; kq++) {
        int k = 8 * w + kq;
        Wp[kq] = pk2(W[(2 * lane) * H + k], W[(2 * lane + 1) * H + k]);
    }
    const float2 b2 = reinterpret_cast<const float2*>(b)[lane];
    const float2 g2 = reinterpret_cast<const float2*>(gamma)[lane];
    const float2 e2 = reinterpret_cast<const float2*>(beta)[lane];

    __shared__ __align__(16) float s_Sd[8][128];     // duplicated S pairs
    __shared__ unsigned long long s_part[8][8][32];  // [row][kwarp][colpair]

    for (int base = blockIdx.x * 8; base < nv; base += gridDim.x * 8) {
        const int row = base + w;
        int dgi = 0;
        if (row < nv) {
            if (lane == 0) {
                dgi = g_cnt[row];
                g_cnt[row] = 0;  // restore for next launch call
            }
            dgi = __shfl_sync(0xffffffffu, dgi, 0);
            if (lane < 16) {
                float4 s = reinterpret_cast<const float4*>(g_agg)[(long)row * 16 + lane];
                float4* p = reinterpret_cast<float4*>(&s_Sd[w][8 * lane]);
                p[0] = make_float4(s.x, s.x, s.y, s.y);
                p[1] = make_float4(s.z, s.z, s.w, s.w);
            }
        } else if (lane < 16) {
            float4* p = reinterpret_cast<float4*>(&s_Sd[w][8 * lane]);
            p[0] = make_float4(0.f, 0.f, 0.f, 0.f);
            p[1] = make_float4(0.f, 0.f, 0.f, 0.f);
        }
        __syncthreads();

#pragma unroll
        for (int r = 0; r < 8; r++) {
            const ulonglong2* sd =
                reinterpret_cast<const ulonglong2*>(&s_Sd[r][16 * w]);
            unsigned long long yA = 0ull, yB = 0ull;
#pragma unroll
            for (int t = 0; t < 4; t++) {
                ulonglong2 ss = sd[t];   // broadcast LDS.128
                yA = fma2(Wp[2 * t],     ss.x, yA);
                yB = fma2(Wp[2 * t + 1], ss.y, yB);
            }
            s_part[r][w][lane] = add2(yA, yB);
        }
        __syncthreads();

        if (row < nv) {
            unsigned long long p0 = add2(s_part[w][0][lane], s_part[w][1][lane]);
            unsigned long long p1 = add2(s_part[w][2][lane], s_part[w][3][lane]);
            unsigned long long p2 = add2(s_part[w][4][lane], s_part[w][5][lane]);
            unsigned long long p3 = add2(s_part[w][6][lane], s_part[w][7][lane]);
            unsigned long long yP = add2(add2(p0, p1), add2(p2, p3));
            float y0, y1;
            asm("mov.b64 {%0, %1}, %2;" : "=f"(y0), "=f"(y1) : "l"(yP));

            float dg = (float)dgi;
            float inv = 1.0f / (dg + 1e-6f);
            float v0 = fmaxf((y0 + dg * b2.x) * inv, 0.f);
            float v1 = fmaxf((y1 + dg * b2.y) * inv, 0.f);

            float s1 = v0 + v1;
            float s2 = v0 * v0 + v1 * v1;
#pragma unroll
            for (int off = 16; off > 0; off >>= 1) {
                s1 += __shfl_xor_sync(0xffffffffu, s1, off);
                s2 += __shfl_xor_sync(0xffffffffu, s2, off);
            }
            float mu = s1 * (1.0f / 64.0f);
            float var = s2 * (1.0f / 64.0f) - mu * mu;
            float r = rsqrtf(var + 1e-5f);
            float2 o;
            o.x = (v0 - mu) * r * g2.x + e2.x;
            o.y = (v1 - mu) * r * g2.y + e2.y;
            reinterpret_cast<float2*>(out)[(long)row * 32 + lane] = o;
        }
    }
}

extern "C" void kernel_launch(void* const* d_in, const int* in_sizes, int n_in,
                              void* d_out, int out_size) {
    const float* x_con = (const float*)d_in[0];
    const int* src = (const int*)d_in[1];
    const int* dst = (const int*)d_in[2];
    int wi = 3;
    if (in_sizes[3] != H * H) {
        for (int i = 3; i < n_in; i++)
            if (in_sizes[i] == H * H) { wi = i; break; }
    }
    const float* W = (const float*)d_in[wi];
    const float* b = (const float*)d_in[wi + 1];
    const float* gamma = (const float*)d_in[wi + 2];
    const float* beta = (const float*)d_in[wi + 3];

    int E = in_sizes[1];
    int nv = out_size / H;

    fill_kernel<<<(E + 255) / 256, 256>>>(src, dst, E);
    gather_kernel<<<(nv + 7) / 8, 256>>>((const float4*)x_con, nv);
    gemv_ln_kernel<<<444, 256>>>(W, b, gamma, beta, (float*)d_out, nv);
}